// round 1
// baseline (speedup 1.0000x reference)
#include <cuda_runtime.h>
#include <cuda_bf16.h>
#include <cstdint>
#include <cstddef>

#define BB 32
#define TT 64
#define II 300
#define HH 168
#define CCd 168
#define SS 512
#define VV 50257
#define G4 672   // 4*H
#define ICK (II+CCd) // 468

// ---------------- device scratch (no allocations allowed) ----------------
__device__ float g_seqproj[BB*SS*HH];   // (B,S,H)
__device__ float g_gatesx[BB*TT*G4];    // (B*T, 4H) includes b_ih+b_hh
__device__ float g_hall[BB*TT*HH];      // (B*T, H)
__device__ float g_WhhT[HH*G4];         // [j][gi]
__device__ float g_WihcT[HH*G4];        // [j][gi] (context part of W_ih)
__device__ float g_WsT[HH*CCd];         // [h][c] = att_Ws[c][h]
__device__ float g_bias[G4];

__device__ __forceinline__ float tanh_apx(float x){
    float y; asm("tanh.approx.f32 %0, %1;" : "=f"(y) : "f"(x)); return y;
}
__device__ __forceinline__ float sigmoid_acc(float x){
    return 1.0f / (1.0f + expf(-x));
}

// ---------------- prep: transposes + bias fold ----------------
__global__ void prep_kernel(const float* __restrict__ W_hh,
                            const float* __restrict__ W_ih,
                            const float* __restrict__ att_Ws,
                            const float* __restrict__ b_ih,
                            const float* __restrict__ b_hh)
{
    int idx = blockIdx.x * blockDim.x + threadIdx.x;
    if (idx < HH*G4){
        int gi = idx % G4, j = idx / G4;
        g_WhhT [j*G4 + gi] = W_hh[gi*HH + j];
        g_WihcT[j*G4 + gi] = W_ih[gi*ICK + II + j];
    }
    if (idx < HH*CCd){
        int h = idx / CCd, c = idx % CCd;
        g_WsT[idx] = att_Ws[c*HH + h];  // idx = h*CCd + c
    }
    if (idx < G4) g_bias[idx] = b_ih[idx] + b_hh[idx];
}

// ---------------- generic C = A * B^T (+bias), fp32 ----------------
// A: (M,K) lda   B: (N,K) ldb   C: (M,N) ldc.  M must be multiple of 128.
#define GBM 128
#define GBN 64
#define GBK 16
#define ASTRIDE 132
#define BSTRIDE 68

__global__ void __launch_bounds__(256)
gemm_abt(const float* __restrict__ A, const float* __restrict__ B,
         const float* __restrict__ bias, float* __restrict__ C,
         int M, int N, int K, int lda, int ldb, int ldc)
{
    __shared__ float As[GBK*ASTRIDE];
    __shared__ float Bs[GBK*BSTRIDE];

    const int m0 = blockIdx.y * GBM;
    const int n0 = blockIdx.x * GBN;
    const int tid = threadIdx.x;
    const int tx = tid & 15;        // 0..15 -> 4 cols each
    const int ty = tid >> 4;        // 0..15 -> 8 rows each
    const int lm = tid >> 2;        // 0..63
    const int lk = (tid & 3) * 4;   // 0,4,8,12

    float acc[8][4];
    #pragma unroll
    for (int r = 0; r < 8; r++)
        #pragma unroll
        for (int c = 0; c < 4; c++) acc[r][c] = 0.f;

    const int ntiles = (K + GBK - 1) / GBK;
    for (int kt = 0; kt < ntiles; kt++){
        const int k0 = kt * GBK;
        // ---- load A tile (two 64-row halves) ----
        #pragma unroll
        for (int half = 0; half < 2; half++){
            int m = lm + half*64;
            const float* ap = A + (size_t)(m0 + m) * lda + (k0 + lk);
            float4 av;
            if (k0 + lk + 3 < K){
                av = *reinterpret_cast<const float4*>(ap);
            } else {
                av.x = (k0+lk+0 < K) ? ap[0] : 0.f;
                av.y = (k0+lk+1 < K) ? ap[1] : 0.f;
                av.z = (k0+lk+2 < K) ? ap[2] : 0.f;
                av.w = (k0+lk+3 < K) ? ap[3] : 0.f;
            }
            As[(lk+0)*ASTRIDE + m] = av.x;
            As[(lk+1)*ASTRIDE + m] = av.y;
            As[(lk+2)*ASTRIDE + m] = av.z;
            As[(lk+3)*ASTRIDE + m] = av.w;
        }
        // ---- load B tile ----
        {
            int n = lm;
            float4 bv = make_float4(0.f,0.f,0.f,0.f);
            if (n0 + n < N){
                const float* bp = B + (size_t)(n0 + n) * ldb + (k0 + lk);
                if (k0 + lk + 3 < K){
                    bv = *reinterpret_cast<const float4*>(bp);
                } else {
                    bv.x = (k0+lk+0 < K) ? bp[0] : 0.f;
                    bv.y = (k0+lk+1 < K) ? bp[1] : 0.f;
                    bv.z = (k0+lk+2 < K) ? bp[2] : 0.f;
                    bv.w = (k0+lk+3 < K) ? bp[3] : 0.f;
                }
            }
            Bs[(lk+0)*BSTRIDE + n] = bv.x;
            Bs[(lk+1)*BSTRIDE + n] = bv.y;
            Bs[(lk+2)*BSTRIDE + n] = bv.z;
            Bs[(lk+3)*BSTRIDE + n] = bv.w;
        }
        __syncthreads();
        // ---- compute ----
        #pragma unroll
        for (int kk = 0; kk < GBK; kk++){
            float4 b4 = *reinterpret_cast<const float4*>(&Bs[kk*BSTRIDE + tx*4]);
            float4 a0 = *reinterpret_cast<const float4*>(&As[kk*ASTRIDE + ty*8]);
            float4 a1 = *reinterpret_cast<const float4*>(&As[kk*ASTRIDE + ty*8 + 4]);
            float ar[8] = {a0.x,a0.y,a0.z,a0.w,a1.x,a1.y,a1.z,a1.w};
            float bc[4] = {b4.x,b4.y,b4.z,b4.w};
            #pragma unroll
            for (int r = 0; r < 8; r++)
                #pragma unroll
                for (int c = 0; c < 4; c++)
                    acc[r][c] = fmaf(ar[r], bc[c], acc[r][c]);
        }
        __syncthreads();
    }
    // ---- epilogue ----
    #pragma unroll
    for (int r = 0; r < 8; r++){
        int m = m0 + ty*8 + r;
        #pragma unroll
        for (int c = 0; c < 4; c++){
            int n = n0 + tx*4 + c;
            if (n < N){
                float v = acc[r][c];
                if (bias) v += __ldg(&bias[n]);
                C[(size_t)m * ldc + n] = v;
            }
        }
    }
}

// ---------------- persistent per-batch recurrence ----------------
__global__ void __launch_bounds__(512)
recur_kernel(const float* __restrict__ context,
             const int*   __restrict__ ctx_len,
             const float* __restrict__ att_Wx,
             const float* __restrict__ att_b,
             const float* __restrict__ att_v)
{
    const int b = blockIdx.x;
    const int tid = threadIdx.x;
    const int warp = tid >> 5, lane = tid & 31;

    __shared__ float sh[HH], sc[HH], sq[HH], sqp[3*HH];
    __shared__ float se[SS], sred[512];
    __shared__ float scp[3*HH], sctx[HH], sg[G4], sv[HH];

    const int len = ctx_len[b];
    if (tid < HH){ sh[tid] = 0.f; sc[tid] = 0.f; sv[tid] = att_v[tid]; }
    __syncthreads();

    const float* spb  = g_seqproj + (size_t)b * SS * HH;
    const float* ctxb = context   + (size_t)b * SS * CCd;

    for (int t = 0; t < TT; t++){
        // ---- q = h @ att_Wx + att_b   (3-way split over j) ----
        if (tid < 3*HH){
            int a = tid % HH, p = tid / HH;
            float acc = 0.f;
            int j0 = p * 56;
            #pragma unroll 8
            for (int j = j0; j < j0 + 56; j++)
                acc = fmaf(sh[j], att_Wx[j*HH + a], acc);
            sqp[tid] = acc;
        }
        __syncthreads();
        if (tid < HH) sq[tid] = att_b[tid] + sqp[tid] + sqp[HH+tid] + sqp[2*HH+tid];
        __syncthreads();

        // ---- attention scores e[s] = v . tanh(q + seq_proj[s]) ----
        for (int s = warp; s < SS; s += 16){
            if (s < len){
                const float* sp = spb + (size_t)s * HH;
                float acc = 0.f;
                for (int a = lane; a < HH; a += 32)
                    acc = fmaf(sv[a], tanh_apx(sq[a] + sp[a]), acc);
                #pragma unroll
                for (int off = 16; off > 0; off >>= 1)
                    acc += __shfl_xor_sync(0xffffffffu, acc, off);
                if (lane == 0) se[s] = acc;
            } else {
                if (lane == 0) se[s] = -1e30f;
            }
        }
        __syncthreads();

        // ---- softmax over e (masked entries are -1e30 -> exp == 0) ----
        sred[tid] = se[tid];
        __syncthreads();
        for (int st = 256; st > 0; st >>= 1){
            if (tid < st) sred[tid] = fmaxf(sred[tid], sred[tid+st]);
            __syncthreads();
        }
        float mx = sred[0];
        __syncthreads();
        float ex = __expf(se[tid] - mx);
        sred[tid] = ex;
        __syncthreads();
        for (int st = 256; st > 0; st >>= 1){
            if (tid < st) sred[tid] += sred[tid+st];
            __syncthreads();
        }
        float inv = 1.0f / sred[0];
        __syncthreads();
        se[tid] = ex * inv;     // se now holds softmax weights
        __syncthreads();

        // ---- attn_ctx = w @ context  (3-way split over s) ----
        if (tid < 3*HH){
            int cc = tid % HH, p = tid / HH;
            float acc = 0.f;
            for (int s = p; s < len; s += 3)
                acc = fmaf(se[s], ctxb[(size_t)s*CCd + cc], acc);
            scp[tid] = acc;
        }
        __syncthreads();
        if (tid < HH) sctx[tid] = scp[tid] + scp[HH+tid] + scp[2*HH+tid];
        __syncthreads();

        // ---- gates = gates_x + ctx @ WihcT + h @ WhhT ----
        {
            const float* gx = g_gatesx + (size_t)(b*TT + t) * G4;
            for (int gi = tid; gi < G4; gi += 512){
                float acc = gx[gi];
                #pragma unroll 4
                for (int j = 0; j < HH; j++){
                    acc = fmaf(sctx[j], g_WihcT[j*G4 + gi], acc);
                    acc = fmaf(sh[j],   g_WhhT [j*G4 + gi], acc);
                }
                sg[gi] = acc;
            }
        }
        __syncthreads();

        // ---- LSTM cell (accurate transcendentals; tiny op count) ----
        if (tid < HH){
            float ig = sigmoid_acc(sg[tid]);
            float fg = sigmoid_acc(sg[HH + tid]);
            float gg = tanhf(sg[2*HH + tid]);
            float og = sigmoid_acc(sg[3*HH + tid]);
            float cn = fg * sc[tid] + ig * gg;
            float hn = og * tanhf(cn);
            sc[tid] = cn;
            sh[tid] = hn;
            g_hall[(size_t)(b*TT + t) * HH + tid] = hn;
        }
        __syncthreads();
    }
}

// ---------------- launch ----------------
extern "C" void kernel_launch(void* const* d_in, const int* in_sizes, int n_in,
                              void* d_out, int out_size)
{
    const float* x        = (const float*)d_in[0];   // (B,T,I)
    const float* context  = (const float*)d_in[1];   // (B,S,C)
    const int*   ctx_len  = (const int*)  d_in[2];   // (B,)
    const float* W_ih     = (const float*)d_in[3];   // (4H, I+C)
    const float* W_hh     = (const float*)d_in[4];   // (4H, H)
    const float* b_ih     = (const float*)d_in[5];
    const float* b_hh     = (const float*)d_in[6];
    const float* att_Wx   = (const float*)d_in[7];   // (H,H)
    const float* att_Ws   = (const float*)d_in[8];   // (C,H)
    const float* att_b    = (const float*)d_in[9];
    const float* att_v    = (const float*)d_in[10];
    const float* W_dec    = (const float*)d_in[11];  // (V,H)
    float* out = (float*)d_out;                      // (B,T,V)

    float *p_seqproj, *p_gatesx, *p_hall, *p_WsT, *p_bias;
    cudaGetSymbolAddress((void**)&p_seqproj, g_seqproj);
    cudaGetSymbolAddress((void**)&p_gatesx,  g_gatesx);
    cudaGetSymbolAddress((void**)&p_hall,    g_hall);
    cudaGetSymbolAddress((void**)&p_WsT,     g_WsT);
    cudaGetSymbolAddress((void**)&p_bias,    g_bias);

    // 1) transposes + bias fold
    prep_kernel<<<(HH*G4 + 255)/256, 256>>>(W_hh, W_ih, att_Ws, b_ih, b_hh);

    // 2) seq_proj = context @ att_Ws    (M=B*S, N=H, K=C)
    {
        dim3 grid((HH + GBN - 1)/GBN, (BB*SS)/GBM);
        gemm_abt<<<grid, 256>>>(context, p_WsT, nullptr, p_seqproj,
                                BB*SS, HH, CCd, CCd, CCd, HH);
    }
    // 3) gates_x = x @ W_ih[:, :I]^T + (b_ih + b_hh)   (M=B*T, N=4H, K=I)
    {
        dim3 grid((G4 + GBN - 1)/GBN, (BB*TT)/GBM);
        gemm_abt<<<grid, 256>>>(x, W_ih, p_bias, p_gatesx,
                                BB*TT, G4, II, II, ICK, G4);
    }
    // 4) recurrence: attention + LSTM, one CTA per batch
    recur_kernel<<<BB, 512>>>(context, ctx_len, att_Wx, att_b, att_v);

    // 5) decode: out = h_all @ W_dec^T  (M=B*T, N=V, K=H)
    {
        dim3 grid((VV + GBN - 1)/GBN, (BB*TT)/GBM);
        gemm_abt<<<grid, 256>>>(p_hall, W_dec, nullptr, out,
                                BB*TT, VV, HH, HH, HH, VV);
    }
}

// round 4
// speedup vs baseline: 1.3700x; 1.3700x over previous
#include <cuda_runtime.h>
#include <cuda_bf16.h>
#include <cstdint>
#include <cstddef>

#define BB 32
#define TT 64
#define II 300
#define HH 168
#define CCd 168
#define SS 512
#define VV 50257
#define G4 672   // 4*H
#define ICK (II+CCd) // 468

// ---------------- device scratch (no allocations allowed) ----------------
__device__ float g_seqproj[BB*SS*HH];   // (B,S,H)
__device__ float g_gatesx[BB*TT*G4];    // (B*T, 4H) includes b_ih+b_hh
__device__ float g_hall[BB*TT*HH];      // (B*T, H)
__device__ float g_WhhT[HH*G4];         // [j][gi]
__device__ float g_WihcT[HH*G4];        // [j][gi] (context part of W_ih)
__device__ float g_WsT[HH*CCd];         // [h][c] = att_Ws[c][h]
__device__ float g_bias[G4];

__device__ __forceinline__ float tanh_apx(float x){
    float y; asm("tanh.approx.f32 %0, %1;" : "=f"(y) : "f"(x)); return y;
}
__device__ __forceinline__ float sigmoid_acc(float x){
    return 1.0f / (1.0f + expf(-x));
}

// ---------------- prep: transposes + bias fold ----------------
__global__ void prep_kernel(const float* __restrict__ W_hh,
                            const float* __restrict__ W_ih,
                            const float* __restrict__ att_Ws,
                            const float* __restrict__ b_ih,
                            const float* __restrict__ b_hh)
{
    int idx = blockIdx.x * blockDim.x + threadIdx.x;
    if (idx < HH*G4){
        int gi = idx % G4, j = idx / G4;
        g_WhhT [j*G4 + gi] = W_hh[gi*HH + j];
        g_WihcT[j*G4 + gi] = W_ih[gi*ICK + II + j];
    }
    if (idx < HH*CCd){
        g_WsT[idx] = att_Ws[(idx % CCd)*HH + (idx / CCd)];
    }
    if (idx < G4) g_bias[idx] = b_ih[idx] + b_hh[idx];
}

// ---------------- SGEMM: C = A * B^T (+bias) ----------------
// A: (M,K) lda   B: (N,K) ldb   C: (M,N) ldc.  M must be multiple of 128.
// 128x128x8 tile, 256 threads, 8x8 microtile (4+4 split), double-buffered.
// NOTE: vectorized C stores only when ldc % 4 == 0 (decode ldc=50257 is odd
// -> scalar stores; misaligned STG.128 traps on sm_100a).
__global__ void __launch_bounds__(256, 2)
sgemm128(const float* __restrict__ A, const float* __restrict__ B,
         const float* __restrict__ bias, float* __restrict__ C,
         int M, int N, int K, int lda, int ldb, int ldc)
{
    __shared__ float As[2][8][128];
    __shared__ float Bs[2][8][128];

    const int m0 = blockIdx.y * 128;
    const int n0 = blockIdx.x * 128;
    const int tid = threadIdx.x;
    const int lrow = tid >> 1;          // 0..127
    const int lk   = (tid & 1) * 4;     // 0 or 4
    const int tx   = tid & 15;          // n-group
    const int ty   = tid >> 4;          // m-group

    const float* aptr = A + (size_t)(m0 + lrow) * lda + lk;
    const bool  bvalid = (n0 + lrow) < N;
    const float* bptr = B + (size_t)(bvalid ? (n0 + lrow) : 0) * ldb + lk;

    float acc[8][8];
    #pragma unroll
    for (int i = 0; i < 8; i++)
        #pragma unroll
        for (int j = 0; j < 8; j++) acc[i][j] = 0.f;

    const int ntiles = (K + 7) >> 3;

    auto loadA = [&](int k0) -> float4 {
        float4 v;
        if (k0 + lk + 3 < K){
            v = *reinterpret_cast<const float4*>(aptr + k0);
        } else {
            v.x = (k0+lk+0 < K) ? aptr[k0+0] : 0.f;
            v.y = (k0+lk+1 < K) ? aptr[k0+1] : 0.f;
            v.z = (k0+lk+2 < K) ? aptr[k0+2] : 0.f;
            v.w = (k0+lk+3 < K) ? aptr[k0+3] : 0.f;
        }
        return v;
    };
    auto loadB = [&](int k0) -> float4 {
        float4 v = make_float4(0.f, 0.f, 0.f, 0.f);
        if (bvalid){
            if (k0 + lk + 3 < K){
                v = *reinterpret_cast<const float4*>(bptr + k0);
            } else {
                v.x = (k0+lk+0 < K) ? bptr[k0+0] : 0.f;
                v.y = (k0+lk+1 < K) ? bptr[k0+1] : 0.f;
                v.z = (k0+lk+2 < K) ? bptr[k0+2] : 0.f;
                v.w = (k0+lk+3 < K) ? bptr[k0+3] : 0.f;
            }
        }
        return v;
    };

    // prime buffer 0
    {
        float4 av = loadA(0), bv = loadB(0);
        As[0][lk+0][lrow] = av.x; As[0][lk+1][lrow] = av.y;
        As[0][lk+2][lrow] = av.z; As[0][lk+3][lrow] = av.w;
        Bs[0][lk+0][lrow] = bv.x; Bs[0][lk+1][lrow] = bv.y;
        Bs[0][lk+2][lrow] = bv.z; Bs[0][lk+3][lrow] = bv.w;
    }
    __syncthreads();

    int cur = 0;
    for (int kt = 0; kt < ntiles; kt++){
        const bool hasnext = (kt + 1) < ntiles;
        float4 an, bn;
        if (hasnext){ an = loadA((kt+1) << 3); bn = loadB((kt+1) << 3); }

        #pragma unroll
        for (int kk = 0; kk < 8; kk++){
            float4 a0 = *reinterpret_cast<const float4*>(&As[cur][kk][ty*4]);
            float4 a1 = *reinterpret_cast<const float4*>(&As[cur][kk][64 + ty*4]);
            float4 b0 = *reinterpret_cast<const float4*>(&Bs[cur][kk][tx*4]);
            float4 b1 = *reinterpret_cast<const float4*>(&Bs[cur][kk][64 + tx*4]);
            float ar[8] = {a0.x,a0.y,a0.z,a0.w,a1.x,a1.y,a1.z,a1.w};
            float br[8] = {b0.x,b0.y,b0.z,b0.w,b1.x,b1.y,b1.z,b1.w};
            #pragma unroll
            for (int i = 0; i < 8; i++)
                #pragma unroll
                for (int j = 0; j < 8; j++)
                    acc[i][j] = fmaf(ar[i], br[j], acc[i][j]);
        }

        if (hasnext){
            int nxt = cur ^ 1;
            As[nxt][lk+0][lrow] = an.x; As[nxt][lk+1][lrow] = an.y;
            As[nxt][lk+2][lrow] = an.z; As[nxt][lk+3][lrow] = an.w;
            Bs[nxt][lk+0][lrow] = bn.x; Bs[nxt][lk+1][lrow] = bn.y;
            Bs[nxt][lk+2][lrow] = bn.z; Bs[nxt][lk+3][lrow] = bn.w;
            __syncthreads();
            cur = nxt;
        }
    }

    // epilogue
    float bb[8];
    #pragma unroll
    for (int jg = 0; jg < 2; jg++){
        #pragma unroll
        for (int j = 0; j < 4; j++){
            int n = n0 + jg*64 + tx*4 + j;
            bb[jg*4 + j] = (bias && n < N) ? __ldg(&bias[n]) : 0.f;
        }
    }
    const bool vec_ok = ((ldc & 3) == 0);   // row base 16B-aligned for every m
    #pragma unroll
    for (int i = 0; i < 8; i++){
        int m = m0 + ((i < 4) ? (ty*4 + i) : (64 + ty*4 + (i - 4)));
        float* crow = C + (size_t)m * ldc;
        #pragma unroll
        for (int jg = 0; jg < 2; jg++){
            int n = n0 + jg*64 + tx*4;
            if (vec_ok && (n + 3 < N)){
                float4 v;
                v.x = acc[i][jg*4+0] + bb[jg*4+0];
                v.y = acc[i][jg*4+1] + bb[jg*4+1];
                v.z = acc[i][jg*4+2] + bb[jg*4+2];
                v.w = acc[i][jg*4+3] + bb[jg*4+3];
                *reinterpret_cast<float4*>(crow + n) = v;
            } else {
                #pragma unroll
                for (int j = 0; j < 4; j++)
                    if (n + j < N) crow[n + j] = acc[i][jg*4+j] + bb[jg*4+j];
            }
        }
    }
}

// ---------------- persistent per-batch recurrence ----------------
__global__ void __launch_bounds__(512)
recur_kernel(const float* __restrict__ context,
             const int*   __restrict__ ctx_len,
             const float* __restrict__ att_Wx,
             const float* __restrict__ att_b,
             const float* __restrict__ att_v)
{
    const int b = blockIdx.x;
    const int tid = threadIdx.x;
    const int warp = tid >> 5, lane = tid & 31;

    __shared__ float sh[HH], sc[HH], sq[HH], sv[HH], sctx[HH];
    __shared__ float se[SS], sred[512];
    __shared__ float sg[G4];
    __shared__ float sbig[3*G4];   // 2016: partial buffers (aliased across phases)

    const int len = ctx_len[b];
    if (tid < HH){ sh[tid] = 0.f; sc[tid] = 0.f; sv[tid] = att_v[tid]; }
    __syncthreads();

    const float* spb  = g_seqproj + (size_t)b * SS * HH;
    const float* ctxb = context   + (size_t)b * SS * CCd;

    for (int t = 0; t < TT; t++){
        // ---- q = h @ att_Wx + att_b   (3-way split over j) ----
        if (tid < 3*HH){
            int a = tid % HH, p = tid / HH;
            float acc = 0.f;
            int j0 = p * 56;
            #pragma unroll 8
            for (int j = j0; j < j0 + 56; j++)
                acc = fmaf(sh[j], att_Wx[j*HH + a], acc);
            sbig[tid] = acc;
        }
        __syncthreads();
        if (tid < HH) sq[tid] = att_b[tid] + sbig[tid] + sbig[HH+tid] + sbig[2*HH+tid];
        __syncthreads();

        // ---- attention scores e[s] = v . tanh(q + seq_proj[s]) ----
        for (int s = warp; s < SS; s += 16){
            if (s < len){
                const float* sp = spb + (size_t)s * HH;
                float acc = 0.f;
                for (int a = lane; a < HH; a += 32)
                    acc = fmaf(sv[a], tanh_apx(sq[a] + sp[a]), acc);
                #pragma unroll
                for (int off = 16; off > 0; off >>= 1)
                    acc += __shfl_xor_sync(0xffffffffu, acc, off);
                if (lane == 0) se[s] = acc;
            } else {
                if (lane == 0) se[s] = -1e30f;
            }
        }
        __syncthreads();

        // ---- softmax over e ----
        sred[tid] = se[tid];
        __syncthreads();
        for (int st = 256; st > 0; st >>= 1){
            if (tid < st) sred[tid] = fmaxf(sred[tid], sred[tid+st]);
            __syncthreads();
        }
        float mx = sred[0];
        __syncthreads();
        float ex = __expf(se[tid] - mx);
        sred[tid] = ex;
        __syncthreads();
        for (int st = 256; st > 0; st >>= 1){
            if (tid < st) sred[tid] += sred[tid+st];
            __syncthreads();
        }
        float inv = 1.0f / sred[0];
        __syncthreads();
        se[tid] = ex * inv;
        __syncthreads();

        // ---- attn_ctx = w @ context  (3-way split over s) ----
        if (tid < 3*HH){
            int cc = tid % HH, p = tid / HH;
            float acc = 0.f;
            for (int s = p; s < len; s += 3)
                acc = fmaf(se[s], ctxb[(size_t)s*CCd + cc], acc);
            sbig[tid] = acc;
        }
        __syncthreads();
        if (tid < HH) sctx[tid] = sbig[tid] + sbig[HH+tid] + sbig[2*HH+tid];
        __syncthreads();

        // ---- gates partials: float4 over gi, 3-way split over j ----
        if (tid < 504){
            const int p = tid / 168;        // j partition
            const int slot = tid % 168;     // gi quad
            const float* wh = g_WhhT  + slot*4;
            const float* wc = g_WihcT + slot*4;
            float4 acc = make_float4(0.f, 0.f, 0.f, 0.f);
            const int j0 = p * 56;
            #pragma unroll 4
            for (int j = j0; j < j0 + 56; j++){
                float hv = sh[j], cv = sctx[j];
                float4 w1 = *reinterpret_cast<const float4*>(wh + (size_t)j*G4);
                float4 w2 = *reinterpret_cast<const float4*>(wc + (size_t)j*G4);
                acc.x = fmaf(hv, w1.x, fmaf(cv, w2.x, acc.x));
                acc.y = fmaf(hv, w1.y, fmaf(cv, w2.y, acc.y));
                acc.z = fmaf(hv, w1.z, fmaf(cv, w2.z, acc.z));
                acc.w = fmaf(hv, w1.w, fmaf(cv, w2.w, acc.w));
            }
            *reinterpret_cast<float4*>(&sbig[p*G4 + slot*4]) = acc;
        }
        __syncthreads();
        {
            const float* gx = g_gatesx + (size_t)(b*TT + t) * G4;
            for (int gi = tid; gi < G4; gi += 512)
                sg[gi] = gx[gi] + sbig[gi] + sbig[G4+gi] + sbig[2*G4+gi];
        }
        __syncthreads();

        // ---- LSTM cell ----
        if (tid < HH){
            float ig = sigmoid_acc(sg[tid]);
            float fg = sigmoid_acc(sg[HH + tid]);
            float gg = tanhf(sg[2*HH + tid]);
            float og = sigmoid_acc(sg[3*HH + tid]);
            float cn = fg * sc[tid] + ig * gg;
            float hn = og * tanhf(cn);
            sc[tid] = cn;
            sh[tid] = hn;
            g_hall[(size_t)(b*TT + t) * HH + tid] = hn;
        }
        __syncthreads();
    }
}

// ---------------- launch ----------------
extern "C" void kernel_launch(void* const* d_in, const int* in_sizes, int n_in,
                              void* d_out, int out_size)
{
    const float* x        = (const float*)d_in[0];
    const float* context  = (const float*)d_in[1];
    const int*   ctx_len  = (const int*)  d_in[2];
    const float* W_ih     = (const float*)d_in[3];
    const float* W_hh     = (const float*)d_in[4];
    const float* b_ih     = (const float*)d_in[5];
    const float* b_hh     = (const float*)d_in[6];
    const float* att_Wx   = (const float*)d_in[7];
    const float* att_Ws   = (const float*)d_in[8];
    const float* att_b    = (const float*)d_in[9];
    const float* att_v    = (const float*)d_in[10];
    const float* W_dec    = (const float*)d_in[11];
    float* out = (float*)d_out;

    float *p_seqproj, *p_gatesx, *p_hall, *p_WsT, *p_bias;
    cudaGetSymbolAddress((void**)&p_seqproj, g_seqproj);
    cudaGetSymbolAddress((void**)&p_gatesx,  g_gatesx);
    cudaGetSymbolAddress((void**)&p_hall,    g_hall);
    cudaGetSymbolAddress((void**)&p_WsT,     g_WsT);
    cudaGetSymbolAddress((void**)&p_bias,    g_bias);

    // 1) transposes + bias fold
    prep_kernel<<<(HH*G4 + 255)/256, 256>>>(W_hh, W_ih, att_Ws, b_ih, b_hh);

    // 2) seq_proj = context @ att_Ws    (M=B*S=16384, N=H, K=C)
    {
        dim3 grid((HH + 127)/128, (BB*SS)/128);
        sgemm128<<<grid, 256>>>(context, p_WsT, nullptr, p_seqproj,
                                BB*SS, HH, CCd, CCd, CCd, HH);
    }
    // 3) gates_x = x @ W_ih[:, :I]^T + (b_ih+b_hh)  (M=2048, N=4H, K=I)
    {
        dim3 grid((G4 + 127)/128, (BB*TT)/128);
        sgemm128<<<grid, 256>>>(x, W_ih, p_bias, p_gatesx,
                                BB*TT, G4, II, II, ICK, G4);
    }
    // 4) recurrence: attention + LSTM, one CTA per batch
    recur_kernel<<<BB, 512>>>(context, ctx_len, att_Wx, att_b, att_v);

    // 5) decode: out = h_all @ W_dec^T  (M=2048, N=V, K=H)
    {
        dim3 grid((VV + 127)/128, (BB*TT)/128);
        sgemm128<<<grid, 256>>>(p_hall, W_dec, nullptr, out,
                                BB*TT, VV, HH, HH, HH, VV);
    }
}